// round 3
// baseline (speedup 1.0000x reference)
#include <cuda_runtime.h>
#include <cstdint>
#include <cfloat>
#include <math.h>

#define NNODES 50000
#define NEDGES 800000
#define TOPK   10
#define NEG_SLOPE 0.2f

// ---------------- scratch (device globals; no allocations anywhere) ----------------
__device__ float g_xl   [(size_t)NNODES * 256];
__device__ float g_h1   [(size_t)NNODES * 256];
__device__ float g_h2   [(size_t)NNODES * 64];
__device__ float g_as   [NNODES * 4];
__device__ float g_ad   [NNODES * 4];
__device__ float g_alphac[(size_t)NEDGES * 4];
__device__ int   g_counts[NNODES];
__device__ int   g_rowptr[NNODES + 1];
__device__ int   g_cursor[NNODES];
__device__ int   g_src  [NEDGES];
__device__ int   g_dst  [NEDGES];
__device__ int   g_eid  [NEDGES];
__device__ int   g_csrsrc[NEDGES];
__device__ int   g_csrdst[NEDGES];
__device__ float g_selw  [(size_t)NNODES * 4 * TOPK];
__device__ int   g_selsrc[(size_t)NNODES * 4 * TOPK];
__device__ int   g_bsum[64];
__device__ int   g_boff[64];
__device__ int   g_is64;

// ---------------- init: zero counts + dtype detect ----------------
__global__ void k_init(const void* ei, int n) {
    int i = blockIdx.x * blockDim.x + threadIdx.x;
    if (i < n) g_counts[i] = 0;
    if (i == 0) {
        const long long* p = (const long long*)ei;
        int ok = 1;
        for (int j = 0; j < 16; j++) {
            long long v = p[j];
            if (v < 0 || v >= NNODES) ok = 0;
        }
        g_is64 = ok;
    }
}

__global__ void k_prep_edges(const void* ei, int E) {
    int e = blockIdx.x * blockDim.x + threadIdx.x;
    if (e >= E) return;
    int s, d;
    if (g_is64) {
        const long long* p = (const long long*)ei;
        s = (int)p[e];
        d = (int)p[(size_t)E + e];
    } else {
        const int* p = (const int*)ei;
        s = p[e];
        d = p[E + e];
    }
    g_src[e] = s;
    g_dst[e] = d;
    atomicAdd(&g_counts[d], 1);
}

// ---------------- multi-block scan: counts -> rowptr, cursor ----------------
__global__ void k_scan1(int n) {   // grid = ceil(n/1024), 256 threads
    __shared__ int ws[8];
    int b = blockIdx.x, tid = threadIdx.x, lane = tid & 31, wid = tid >> 5;
    int base = b * 1024 + tid * 4;
    int v[4]; int s = 0;
    #pragma unroll
    for (int j = 0; j < 4; j++) {
        int idx = base + j;
        v[j] = (idx < n) ? g_counts[idx] : 0;
        s += v[j];
    }
    int xsc = s;
    #pragma unroll
    for (int off = 1; off < 32; off <<= 1) {
        int t2 = __shfl_up_sync(0xffffffffu, xsc, off);
        if (lane >= off) xsc += t2;
    }
    if (lane == 31) ws[wid] = xsc;
    __syncthreads();
    if (tid == 0) {
        int acc = 0;
        #pragma unroll
        for (int i = 0; i < 8; i++) { acc += ws[i]; ws[i] = acc; }
        g_bsum[b] = acc;
    }
    __syncthreads();
    int pre = (xsc - s) + (wid > 0 ? ws[wid - 1] : 0);
    int run = pre;
    #pragma unroll
    for (int j = 0; j < 4; j++) {
        run += v[j];
        if (base + j < n) g_rowptr[base + j + 1] = run;
    }
}

__global__ void k_scan2(int nb) {   // 1 block, 64 threads
    __shared__ int sh[64];
    int t = threadIdx.x;
    int v = (t < nb) ? g_bsum[t] : 0;
    sh[t] = v;
    __syncthreads();
    for (int off = 1; off < 64; off <<= 1) {
        int add = (t >= off) ? sh[t - off] : 0;
        __syncthreads();
        sh[t] += add;
        __syncthreads();
    }
    if (t < nb) g_boff[t] = sh[t] - v;   // exclusive
}

__global__ void k_scan3(int n) {
    int i = blockIdx.x * blockDim.x + threadIdx.x;
    if (i >= n) return;
    int v = g_rowptr[i + 1] + g_boff[i >> 10];
    g_rowptr[i + 1] = v;
    g_cursor[i] = v - g_counts[i];
    if (i == 0) g_rowptr[0] = 0;
}

__global__ void k_scatter(int E) {
    int e = blockIdx.x * blockDim.x + threadIdx.x;
    if (e >= E) return;
    int d = g_dst[e];
    int p = atomicAdd(&g_cursor[d], 1);
    g_eid[p] = e;
}

__global__ void k_csr(int E) {
    int i = blockIdx.x * blockDim.x + threadIdx.x;
    if (i >= E) return;
    int e = g_eid[i];
    g_csrsrc[i] = g_src[e];
    g_csrdst[i] = g_dst[e];
}

// ---------------- packed-fp32 helpers (sm_103a f32x2; IEEE rn per lane) ----------------
__device__ __forceinline__ unsigned long long pk2(float lo, float hi) {
    unsigned long long r;
    asm("mov.b64 %0, {%1, %2};" : "=l"(r) : "f"(lo), "f"(hi));
    return r;
}
__device__ __forceinline__ void upk2(unsigned long long v, float& lo, float& hi) {
    asm("mov.b64 {%0, %1}, %2;" : "=f"(lo), "=f"(hi) : "l"(v));
}
__device__ __forceinline__ void fma2(unsigned long long& d, unsigned long long a, unsigned long long b) {
    asm("fma.rn.f32x2 %0, %1, %2, %0;" : "+l"(d) : "l"(a), "l"(b));
}

// ---------------- fp32 GEMM (bit-exact to round-1 k_gemm, f32x2 dual-FMA) ----------------
// C[m,n] = sum_k A[m,k]*W[n,k], K = 256, per-element k-order: sequential 0..255.
#define GFETCH(k0) { \
    int gm0 = bm + lrow, gm1 = bm + lrow + 64; \
    ra0 = (gm0 < M) ? *(const float4*)(A + (size_t)gm0 * 256 + (k0) + lcol) : f4z; \
    ra1 = (gm1 < M) ? *(const float4*)(A + (size_t)gm1 * 256 + (k0) + lcol) : f4z; \
    rb0 = *(const float4*)(W + (size_t)(bn + lrow) * 256 + (k0) + lcol); \
    rb1 = *(const float4*)(W + (size_t)(bn + lrow + 64) * 256 + (k0) + lcol); }

#define GSTORE(b) { \
    As[b][lcol+0][lrow] = ra0.x; As[b][lcol+1][lrow] = ra0.y; As[b][lcol+2][lrow] = ra0.z; As[b][lcol+3][lrow] = ra0.w; \
    As[b][lcol+0][lrow+64] = ra1.x; As[b][lcol+1][lrow+64] = ra1.y; As[b][lcol+2][lrow+64] = ra1.z; As[b][lcol+3][lrow+64] = ra1.w; \
    Bs[b][lcol+0][lrow] = rb0.x; Bs[b][lcol+1][lrow] = rb0.y; Bs[b][lcol+2][lrow] = rb0.z; Bs[b][lcol+3][lrow] = rb0.w; \
    Bs[b][lcol+0][lrow+64] = rb1.x; Bs[b][lcol+1][lrow+64] = rb1.y; Bs[b][lcol+2][lrow+64] = rb1.z; Bs[b][lcol+3][lrow+64] = rb1.w; }

__global__ void __launch_bounds__(256) k_gemm(const float* __restrict__ Aext,
                                              const float* __restrict__ W,
                                              int M, int layer) {
    const float* A = (layer == 0) ? Aext : g_h1;
    float* C = g_xl;
    __shared__ float As[2][16][128];
    __shared__ float Bs[2][16][128];
    int tid = threadIdx.x;
    int bm = blockIdx.y * 128, bn = blockIdx.x * 128;
    int tm = (tid >> 4) * 8, tn = (tid & 15) * 8;
    int lrow = tid >> 2, lcol = (tid & 3) * 4;
    const float4 f4z = make_float4(0.f, 0.f, 0.f, 0.f);
    float4 ra0, ra1, rb0, rb1;
    unsigned long long acc[8][4];   // acc[i][jp] = (C[i][2jp], C[i][2jp+1])
    #pragma unroll
    for (int i = 0; i < 8; i++)
        #pragma unroll
        for (int j = 0; j < 4; j++) acc[i][j] = 0ull;

    GFETCH(0); GSTORE(0);
    __syncthreads();
    int buf = 0;
    for (int t = 0; t < 16; t++) {
        if (t < 15) GFETCH((t + 1) * 16);
        #pragma unroll
        for (int kk = 0; kk < 16; kk++) {
            float a[8];
            *(float4*)(a)     = *(const float4*)&As[buf][kk][tm];
            *(float4*)(a + 4) = *(const float4*)&As[buf][kk][tm + 4];
            unsigned long long bp[4];
            const unsigned long long* brow = (const unsigned long long*)&Bs[buf][kk][tn];
            bp[0] = brow[0]; bp[1] = brow[1]; bp[2] = brow[2]; bp[3] = brow[3];
            unsigned long long ad[8];
            #pragma unroll
            for (int i = 0; i < 8; i++) ad[i] = pk2(a[i], a[i]);
            #pragma unroll
            for (int i = 0; i < 8; i++)
                #pragma unroll
                for (int j = 0; j < 4; j++) fma2(acc[i][j], ad[i], bp[j]);
        }
        if (t < 15) GSTORE(buf ^ 1);
        __syncthreads();
        buf ^= 1;
    }
    #pragma unroll
    for (int i = 0; i < 8; i++) {
        int gm = bm + tm + i;
        if (gm < M) {
            float c0, c1, c2, c3, c4, c5, c6, c7;
            upk2(acc[i][0], c0, c1); upk2(acc[i][1], c2, c3);
            upk2(acc[i][2], c4, c5); upk2(acc[i][3], c6, c7);
            *(float4*)(C + (size_t)gm * 256 + bn + tn)     = make_float4(c0, c1, c2, c3);
            *(float4*)(C + (size_t)gm * 256 + bn + tn + 4) = make_float4(c4, c5, c6, c7);
        }
    }
}

// ---------------- attention dots (round-1 exact) ----------------
__global__ void k_attdot(const float* __restrict__ atts, const float* __restrict__ attd, int n) {
    int warp = blockIdx.x * (blockDim.x >> 5) + (threadIdx.x >> 5);
    int lane = threadIdx.x & 31;
    if (warp >= n) return;
    const float* row = g_xl + (size_t)warp * 256 + lane * 8;
    float4 x0 = *(const float4*)(row);
    float4 x1 = *(const float4*)(row + 4);
    float4 s0 = *(const float4*)(atts + lane * 8);
    float4 s1 = *(const float4*)(atts + lane * 8 + 4);
    float4 d0 = *(const float4*)(attd + lane * 8);
    float4 d1 = *(const float4*)(attd + lane * 8 + 4);
    float ps = x0.x * s0.x + x0.y * s0.y + x0.z * s0.z + x0.w * s0.w
             + x1.x * s1.x + x1.y * s1.y + x1.z * s1.z + x1.w * s1.w;
    float pd = x0.x * d0.x + x0.y * d0.y + x0.z * d0.z + x0.w * d0.w
             + x1.x * d1.x + x1.y * d1.y + x1.z * d1.z + x1.w * d1.w;
    #pragma unroll
    for (int off = 4; off >= 1; off >>= 1) {
        ps += __shfl_xor_sync(0xffffffffu, ps, off);
        pd += __shfl_xor_sync(0xffffffffu, pd, off);
    }
    if ((lane & 7) == 0) {
        int h = lane >> 3;
        g_as[warp * 4 + h] = ps;
        g_ad[warp * 4 + h] = pd;
    }
}

// ---------------- per-edge scores (CSR order; same arithmetic as round 1) ----------------
__device__ __forceinline__ float lrelu(float x) { return x >= 0.f ? x : NEG_SLOPE * x; }

__global__ void k_alphac(int E) {
    int i = blockIdx.x * blockDim.x + threadIdx.x;
    if (i >= E) return;
    int s = g_csrsrc[i], d = g_csrdst[i];
    float4 a = *(const float4*)(g_as + s * 4);
    float4 b = *(const float4*)(g_ad + d * 4);
    float4 r;
    r.x = lrelu(a.x + b.x);
    r.y = lrelu(a.y + b.y);
    r.z = lrelu(a.z + b.z);
    r.w = lrelu(a.w + b.w);
    *(float4*)(g_alphac + (size_t)i * 4) = r;
}

// ---------------- top-K + softmax + compaction (CSR-order output) ----------------
__global__ void k_select(int n) {
    int t = blockIdx.x * blockDim.x + threadIdx.x;
    if (t >= n * 4) return;
    int node = t >> 2, h = t & 3;
    int s = g_rowptr[node], eend = g_rowptr[node + 1];
    float tv[TOPK]; int te[TOPK]; int tp[TOPK];
    int cnt = 0;
    for (int i = s; i < eend; i++) {
        float a = g_alphac[(size_t)i * 4 + h];
        int id = g_eid[i];
        if (cnt < TOPK) {
            int p = cnt++;
            tv[p] = a; te[p] = id; tp[p] = i;
            while (p > 0 && (tv[p] > tv[p - 1] || (tv[p] == tv[p - 1] && te[p] < te[p - 1]))) {
                float fv = tv[p]; tv[p] = tv[p - 1]; tv[p - 1] = fv;
                int e1 = te[p]; te[p] = te[p - 1]; te[p - 1] = e1;
                int p1 = tp[p]; tp[p] = tp[p - 1]; tp[p - 1] = p1;
                p--;
            }
        } else {
            if (tv[TOPK - 1] > a || (tv[TOPK - 1] == a && te[TOPK - 1] < id)) continue;
            tv[TOPK - 1] = a; te[TOPK - 1] = id; tp[TOPK - 1] = i;
            int p = TOPK - 1;
            while (p > 0 && (tv[p] > tv[p - 1] || (tv[p] == tv[p - 1] && te[p] < te[p - 1]))) {
                float fv = tv[p]; tv[p] = tv[p - 1]; tv[p - 1] = fv;
                int e1 = te[p]; te[p] = te[p - 1]; te[p - 1] = e1;
                int p1 = tp[p]; tp[p] = tp[p - 1]; tp[p - 1] = p1;
                p--;
            }
        }
    }
    // softmax stats in descending-alpha order (round-1 bit order)
    float m = (cnt > 0) ? tv[0] : 0.f;
    float den = 0.f;
    for (int j = 0; j < cnt; j++) den += expf(tv[j] - m);
    float inv = (cnt > 0) ? 1.f / den : 0.f;
    // re-sort kept entries by CSR position ascending so aggregation order
    // bit-matches the round-1 full-segment ascending sum
    for (int i2 = 1; i2 < cnt; i2++) {
        float fv = tv[i2]; int p1 = tp[i2];
        int j2 = i2 - 1;
        while (j2 >= 0 && tp[j2] > p1) { tv[j2 + 1] = tv[j2]; tp[j2 + 1] = tp[j2]; j2--; }
        tv[j2 + 1] = fv; tp[j2 + 1] = p1;
    }
    size_t base = (size_t)t * TOPK;
    for (int j = 0; j < TOPK; j++) {
        if (j < cnt) {
            g_selw[base + j] = expf(tv[j] - m) * inv;
            g_selsrc[base + j] = g_csrsrc[tp[j]];
        } else {
            g_selw[base + j] = 0.f;
        }
    }
}

// ---------------- aggregation over selected edges only ----------------
template <int MODE>
__global__ void __launch_bounds__(64) k_agg2(const float* __restrict__ bias, int n) {
    __shared__ float sh[256];
    int node = blockIdx.x;
    int tid = threadIdx.x;
    int head = tid >> 4;
    size_t base = ((size_t)node * 4 + head) * TOPK;
    float a0 = 0.f, a1 = 0.f, a2 = 0.f, a3 = 0.f;
    #pragma unroll
    for (int j = 0; j < TOPK; j++) {
        float w = g_selw[base + j];
        if (w != 0.f) {
            int src = g_selsrc[base + j];
            float4 v = *(const float4*)(g_xl + (size_t)src * 256 + tid * 4);
            a0 += w * v.x; a1 += w * v.y; a2 += w * v.z; a3 += w * v.w;
        }
    }
    if (MODE == 0) {
        float4 b = *(const float4*)(bias + tid * 4);
        *(float4*)(g_h1 + (size_t)node * 256 + tid * 4) =
            make_float4(a0 + b.x, a1 + b.y, a2 + b.z, a3 + b.w);
    } else {
        sh[tid * 4 + 0] = a0; sh[tid * 4 + 1] = a1; sh[tid * 4 + 2] = a2; sh[tid * 4 + 3] = a3;
        __syncthreads();
        int c = tid;
        float v = 0.25f * (sh[c] + sh[64 + c] + sh[128 + c] + sh[192 + c]) + bias[c];
        g_h2[(size_t)node * 64 + c] = v;
    }
}

// ---------------- fused MLP head ----------------
__global__ void __launch_bounds__(128) k_head(const float* __restrict__ W1, const float* __restrict__ b1,
                                              const float* __restrict__ W2, const float* __restrict__ b2,
                                              float* __restrict__ out, int n) {
    __shared__ float xsh[32][64];
    __shared__ float hsh[32][128];
    __shared__ float w2t[128 * 16];
    __shared__ float b2s[16];
    int tid = threadIdx.x;
    int r0 = blockIdx.x * 32;
    for (int i = tid; i < 128 * 16; i += 128) {
        int k = i >> 4, o = i & 15;
        w2t[i] = W2[o * 128 + k];
    }
    if (tid < 16) b2s[tid] = b2[tid];
    for (int i = tid; i < 32 * 16; i += 128) {
        int r = i >> 4, c4 = (i & 15) * 4;
        float4 v = (r0 + r < n) ? *(const float4*)(g_h2 + (size_t)(r0 + r) * 64 + c4)
                                : make_float4(0.f, 0.f, 0.f, 0.f);
        *(float4*)&xsh[r][c4] = v;
    }
    __syncthreads();
    float wreg[64];
    #pragma unroll
    for (int k4 = 0; k4 < 16; k4++) {
        float4 v = *(const float4*)(W1 + tid * 64 + k4 * 4);
        wreg[k4 * 4 + 0] = v.x; wreg[k4 * 4 + 1] = v.y; wreg[k4 * 4 + 2] = v.z; wreg[k4 * 4 + 3] = v.w;
    }
    float bias1 = b1[tid];
    for (int r = 0; r < 32; r++) {
        float sacc = bias1;
        #pragma unroll
        for (int k = 0; k < 64; k++) sacc += wreg[k] * xsh[r][k];
        hsh[r][tid] = fmaxf(sacc, 0.f);
    }
    __syncthreads();
    for (int t = tid; t < 512; t += 128) {
        int r = t >> 4, o = t & 15;
        float sacc = b2s[o];
        #pragma unroll
        for (int k = 0; k < 128; k++) sacc += hsh[r][k] * w2t[k * 16 + o];
        if (r0 + r < n) out[(size_t)(r0 + r) * 16 + o] = sacc;
    }
}

// ---------------- launch ----------------
extern "C" void kernel_launch(void* const* d_in, const int* in_sizes, int n_in,
                              void* d_out, int out_size) {
    (void)n_in; (void)out_size;
    const float* x   = (const float*)d_in[0];
    const float* W1  = (const float*)d_in[1];
    const float* as1 = (const float*)d_in[2];
    const float* ad1 = (const float*)d_in[3];
    const float* b1  = (const float*)d_in[4];
    const float* W2  = (const float*)d_in[5];
    const float* as2 = (const float*)d_in[6];
    const float* ad2 = (const float*)d_in[7];
    const float* b2  = (const float*)d_in[8];
    const float* Wl1 = (const float*)d_in[9];
    const float* bl1 = (const float*)d_in[10];
    const float* Wl2 = (const float*)d_in[11];
    const float* bl2 = (const float*)d_in[12];
    const void*  ei  = d_in[13];
    float* out = (float*)d_out;

    int Nn = in_sizes[0] / 256;
    int Ee = in_sizes[13] / 2;
    int nb = (Nn + 1023) / 1024;

    // CSR build
    k_init<<<(Nn + 255) / 256, 256>>>(ei, Nn);
    k_prep_edges<<<(Ee + 255) / 256, 256>>>(ei, Ee);
    k_scan1<<<nb, 256>>>(Nn);
    k_scan2<<<1, 64>>>(nb);
    k_scan3<<<(Nn + 255) / 256, 256>>>(Nn);
    k_scatter<<<(Ee + 255) / 256, 256>>>(Ee);
    k_csr<<<(Ee + 255) / 256, 256>>>(Ee);

    dim3 gg(2, (Nn + 127) / 128);

    // layer 1
    k_gemm<<<gg, 256>>>(x, W1, Nn, 0);
    k_attdot<<<(Nn + 7) / 8, 256>>>(as1, ad1, Nn);
    k_alphac<<<(Ee + 255) / 256, 256>>>(Ee);
    k_select<<<(Nn * 4 + 127) / 128, 128>>>(Nn);
    k_agg2<0><<<Nn, 64>>>(b1, Nn);

    // layer 2
    k_gemm<<<gg, 256>>>(x, W2, Nn, 1);
    k_attdot<<<(Nn + 7) / 8, 256>>>(as2, ad2, Nn);
    k_alphac<<<(Ee + 255) / 256, 256>>>(Ee);
    k_select<<<(Nn * 4 + 127) / 128, 128>>>(Nn);
    k_agg2<1><<<Nn, 64>>>(b2, Nn);

    // head
    k_head<<<(Nn + 31) / 32, 128>>>(Wl1, bl1, Wl2, bl2, out, Nn);
}